// round 4
// baseline (speedup 1.0000x reference)
#include <cuda_runtime.h>
#include <cstdint>
#include <cstddef>

// ---------------------------------------------------------------------------
// Problem constants
// ---------------------------------------------------------------------------
#define TOKENS   8192
#define IN_F     4096
#define OUT_F    4096
#define GS       128

// GEMM tiling
#define BM 128
#define BN 128
#define BK 32
#define STAGES 3                      // 96KB smem -> 2 CTAs/SM
#define NCHUNK (IN_F / BK)            // 128
#define GRID_N (OUT_F / BN)           // 32
#define GRID_M (TOKENS / BM)          // 64

#define OFF_B       (BM * BK * 4)     // 16384 (A tile bytes)
#define STAGE_BYTES ((BM + BN) * BK * 4)   // 32768
#define GEMM_SMEM   (STAGES * STAGE_BYTES) // 98304

// ---------------------------------------------------------------------------
// Device scratch (static -- no cudaMalloc anywhere)
// Layout of g_x / g_w: within each 32-float K-chunk, column c is stored at
// position p = (c%8)*4 + (c/8).  One 16B chunk = the 4 k-steps of one MMA
// fragment slot -> every fragment load in the GEMM is a single LDS.128.
// ---------------------------------------------------------------------------
__device__ float g_x[(size_t)TOKENS * IN_F];
__device__ float g_w[(size_t)OUT_F * IN_F];
__device__ int   g_inv[IN_F];

// ---------------------------------------------------------------------------
// PTX helpers (family-common only)
// ---------------------------------------------------------------------------
__device__ __forceinline__ uint32_t smem_u32(const void* p) {
    uint32_t a;
    asm("{ .reg .u64 t; cvta.to.shared.u64 t, %1; cvt.u32.u64 %0, t; }"
        : "=r"(a) : "l"(p));
    return a;
}

__device__ __forceinline__ void cp_async16(uint32_t smem_addr, const void* gptr) {
    asm volatile("cp.async.cg.shared.global [%0], [%1], 16;"
                 :: "r"(smem_addr),
                    "l"((unsigned long long)__cvta_generic_to_global(gptr))
                 : "memory");
}
#define CP_COMMIT() asm volatile("cp.async.commit_group;" ::: "memory")
#define CP_WAIT(n)  asm volatile("cp.async.wait_group %0;" :: "n"(n) : "memory")

#define LDS128(v, addr)                                                        \
    asm volatile("ld.shared.v4.b32 {%0,%1,%2,%3}, [%4];"                       \
                 : "=r"((v)[0]), "=r"((v)[1]), "=r"((v)[2]), "=r"((v)[3])      \
                 : "r"(addr))

__device__ __forceinline__ uint32_t f2tf32(float f) {
    uint32_t v;
    asm("cvt.rna.tf32.f32 %0, %1;" : "=r"(v) : "f"(f));
    return v;
}

#define MMA_TF32(d, a0, a1, a2, a3, b0, b1)                                    \
    asm volatile(                                                              \
        "mma.sync.aligned.m16n8k8.row.col.f32.tf32.tf32.f32 "                  \
        "{%0,%1,%2,%3}, {%4,%5,%6,%7}, {%8,%9}, {%0,%1,%2,%3};"                \
        : "+f"((d)[0]), "+f"((d)[1]), "+f"((d)[2]), "+f"((d)[3])               \
        : "r"(a0), "r"(a1), "r"(a2), "r"(a3), "r"(b0), "r"(b1))

// position of column c (0..31) inside its permuted 32-float chunk
__device__ __forceinline__ int permpos(int c) {
    return ((c & 7) << 2) + ((c >> 3) & 3);
}

// ---------------------------------------------------------------------------
// Prep kernels
// ---------------------------------------------------------------------------
__global__ void inv_perm_kernel(const int* __restrict__ perm) {
    int j = blockIdx.x * blockDim.x + threadIdx.x;
    if (j < IN_F) g_inv[perm[j]] = j;
}

// Dequantize + fold activation permutation into W; tf32-round; permuted store.
__global__ void prep_w_kernel(const int* __restrict__ wp, const float* __restrict__ ws) {
    __shared__ int   srow[IN_F / 2];
    __shared__ float sscale[IN_F / GS];
    int o = blockIdx.x;
    int tid = threadIdx.x;
    for (int i = tid; i < IN_F / 2; i += 256) srow[i] = wp[(size_t)o * (IN_F / 2) + i];
    if (tid < IN_F / GS) sscale[tid] = ws[(size_t)o * (IN_F / GS) + tid];
    __syncthreads();
    for (int k = tid; k < IN_F; k += 256) {
        int j = g_inv[k];                        // source (pre-perm) column
        int b = srow[j >> 1];
        int q = (((j & 1) ? (b >> 4) : b) & 0xF) - 8;
        float w = (float)q * sscale[j >> 7];     // group = j / 128
        int pos = (k & ~31) + permpos(k & 31);
        g_w[(size_t)o * IN_F + pos] = __uint_as_float(f2tf32(w));
    }
}

// Round x to tf32 (rna); permuted store (4 consecutive cols -> stride-4 slots).
__global__ void prep_x_kernel(const float4* __restrict__ x) {
    int i = blockIdx.x * blockDim.x + threadIdx.x;   // exact grid
    float4 v = x[i];
    int c0 = (i * 4) & (IN_F - 1);                   // column of v.x
    size_t base = ((size_t)i * 4 - c0) + (c0 & ~31) + permpos(c0 & 31);
    g_x[base]      = __uint_as_float(f2tf32(v.x));
    g_x[base + 4]  = __uint_as_float(f2tf32(v.y));
    g_x[base + 8]  = __uint_as_float(f2tf32(v.z));
    g_x[base + 12] = __uint_as_float(f2tf32(v.w));
}

// ---------------------------------------------------------------------------
// GEMM: 128x128 CTA, 3-stage cp.async pipeline, m16n8k8 tf32, LDS.128 frags.
// Warp grid 4(M) x 2(N); warp tile 32x64. 2 CTAs/SM.
// Smem swizzle: byte offset within a 128B row is XORed by (row&1)<<6.
// ---------------------------------------------------------------------------
__device__ __forceinline__ void load_stage(uint32_t sbase, int s, int chunk,
                                           int m0, int n0, int tid) {
    uint32_t st = sbase + (uint32_t)s * STAGE_BYTES;
    const float* gA = g_x + (size_t)m0 * IN_F + chunk * BK;
    const float* gB = g_w + (size_t)n0 * IN_F + chunk * BK;
    #pragma unroll
    for (int it = 0; it < 4; ++it) {
        int u = tid + it * 256;                  // 0..1023
        int r = u >> 3, seg = u & 7;             // row, 16B-seg within 128B row
        uint32_t so = (uint32_t)(r * 128) + (uint32_t)((seg * 16) ^ ((r & 1) << 6));
        cp_async16(st + so,         gA + (size_t)r * IN_F + seg * 4);
        cp_async16(st + OFF_B + so, gB + (size_t)r * IN_F + seg * 4);
    }
}

__global__ void __launch_bounds__(256, 2)
gemm_kernel(const float* __restrict__ bias, float* __restrict__ out) {
    extern __shared__ char smem[];
    const uint32_t sbase = smem_u32(smem);
    const int tid  = threadIdx.x;
    const int wid  = tid >> 5;
    const int lane = tid & 31;
    const int bid  = blockIdx.x;
    const int n0 = (bid & (GRID_N - 1)) * BN;    // n-fast: W slab stays in L2
    const int m0 = (bid / GRID_N) * BM;

    const int wm = wid >> 1;                     // 0..3
    const int wn = wid & 1;                      // 0..1
    const int g  = lane >> 2;                    // 0..7
    const int t  = lane & 3;                     // 0..3
    // column-group byte offsets within a row (pre-XORed by row parity = g&1)
    const uint32_t o_t  = (uint32_t)((t * 16) ^ ((g & 1) << 6));
    const uint32_t o_t4 = o_t ^ 64u;

    float acc[2][8][4];
    #pragma unroll
    for (int i = 0; i < 2; ++i)
        #pragma unroll
        for (int j = 0; j < 8; ++j)
            #pragma unroll
            for (int c = 0; c < 4; ++c) acc[i][j][c] = 0.0f;

    #pragma unroll
    for (int c = 0; c < STAGES - 1; ++c) {
        load_stage(sbase, c, c, m0, n0, tid);
        CP_COMMIT();
    }

    const uint32_t aRow0 = (uint32_t)((wm * 32 + g) * 128);          // mi=0, +8 row = +1024
    const uint32_t bRow0 = (uint32_t)((wn * 64 + g) * 128) + OFF_B;  // j=0,   +8 row = +1024

    int s_cons = 0, s_prod = STAGES - 1;

    #pragma unroll 1
    for (int i = 0; i < NCHUNK; ++i) {
        CP_WAIT(STAGES - 2);
        __syncthreads();
        if (i + STAGES - 1 < NCHUNK) {
            load_stage(sbase, s_prod, i + STAGES - 1, m0, n0, tid);
            if (++s_prod == STAGES) s_prod = 0;
        }
        CP_COMMIT();

        const uint32_t st = sbase + (uint32_t)s_cons * STAGE_BYTES;
        if (++s_cons == STAGES) s_cons = 0;

        // A fragments for the whole chunk: a[mi][slot][ks]
        // slot 0 = a0 (row g),  1 = a1 (row g+8), 2 = a2 (row g, t+4), 3 = a3 (row g+8, t+4)
        uint32_t A[2][4][4];
        #pragma unroll
        for (int mi = 0; mi < 2; ++mi) {
            uint32_t r0 = st + aRow0 + (uint32_t)(mi * 16 * 128);
            uint32_t r1 = r0 + 8 * 128;
            LDS128(A[mi][0], r0 + o_t);
            LDS128(A[mi][1], r1 + o_t);
            LDS128(A[mi][2], r0 + o_t4);
            LDS128(A[mi][3], r1 + o_t4);
        }

        // B in pairs of j (keeps register pressure in budget)
        #pragma unroll
        for (int jp = 0; jp < 4; ++jp) {
            uint32_t B[2][2][4];                 // [j in pair][b0/b1][ks]
            #pragma unroll
            for (int jj = 0; jj < 2; ++jj) {
                uint32_t nb = st + bRow0 + (uint32_t)((jp * 2 + jj) * 8 * 128);
                LDS128(B[jj][0], nb + o_t);
                LDS128(B[jj][1], nb + o_t4);
            }
            #pragma unroll
            for (int ks = 0; ks < 4; ++ks)
                #pragma unroll
                for (int jj = 0; jj < 2; ++jj)
                    #pragma unroll
                    for (int mi = 0; mi < 2; ++mi)
                        MMA_TF32(acc[mi][jp * 2 + jj],
                                 A[mi][0][ks], A[mi][1][ks], A[mi][2][ks], A[mi][3][ks],
                                 B[jj][0][ks], B[jj][1][ks]);
        }
    }

    // Epilogue: c0/c1 at (row, 2t), c2/c3 at (row+8, 2t); add bias, float2 stores
    #pragma unroll
    for (int mi = 0; mi < 2; ++mi) {
        const int row0 = m0 + wm * 32 + mi * 16 + g;
        #pragma unroll
        for (int j = 0; j < 8; ++j) {
            const int col = n0 + wn * 64 + j * 8 + t * 2;
            const float2 b2 = *reinterpret_cast<const float2*>(bias + col);
            float2 v0, v1;
            v0.x = acc[mi][j][0] + b2.x;  v0.y = acc[mi][j][1] + b2.y;
            v1.x = acc[mi][j][2] + b2.x;  v1.y = acc[mi][j][3] + b2.y;
            *reinterpret_cast<float2*>(out + (size_t)row0 * OUT_F + col) = v0;
            *reinterpret_cast<float2*>(out + (size_t)(row0 + 8) * OUT_F + col) = v1;
        }
    }
}

// ---------------------------------------------------------------------------
// Launch
// ---------------------------------------------------------------------------
extern "C" void kernel_launch(void* const* d_in, const int* in_sizes, int n_in,
                              void* d_out, int out_size) {
    const float* x    = (const float*)d_in[0];
    const int*   wp   = (const int*)d_in[1];
    const float* ws   = (const float*)d_in[2];
    const int*   perm = (const int*)d_in[3];
    const float* bias = (const float*)d_in[4];
    float* out = (float*)d_out;

    inv_perm_kernel<<<IN_F / 256, 256>>>(perm);
    prep_w_kernel<<<OUT_F, 256>>>(wp, ws);
    prep_x_kernel<<<(TOKENS * (IN_F / 4)) / 256, 256>>>((const float4*)x);

    cudaFuncSetAttribute(gemm_kernel, cudaFuncAttributeMaxDynamicSharedMemorySize,
                         GEMM_SMEM);
    gemm_kernel<<<GRID_M * GRID_N, 256, GEMM_SMEM>>>(bias, out);
}

// round 5
// speedup vs baseline: 2.4232x; 2.4232x over previous
#include <cuda_runtime.h>
#include <cuda_fp16.h>
#include <cstdint>
#include <cstddef>

// ---------------------------------------------------------------------------
// Problem constants
// ---------------------------------------------------------------------------
#define TOKENS   8192
#define IN_F     4096
#define OUT_F    4096
#define GS       128

// GEMM tiling (fp16): BK = 64 halves = 128B rows
#define BM 128
#define BN 128
#define BK 64
#define STAGES 3                      // 96KB smem -> 2 CTAs/SM
#define NCHUNK (IN_F / BK)            // 64
#define GRID_N (OUT_F / BN)           // 32
#define GRID_M (TOKENS / BM)          // 64

#define OFF_B       (BM * BK * 2)     // 16384 (A tile bytes)
#define STAGE_BYTES ((BM + BN) * BK * 2)   // 32768
#define GEMM_SMEM   (STAGES * STAGE_BYTES) // 98304

// ---------------------------------------------------------------------------
// Device scratch (static -- no cudaMalloc anywhere)
// ---------------------------------------------------------------------------
__device__ __half g_x[(size_t)TOKENS * IN_F];   // x rounded to fp16
__device__ __half g_w[(size_t)OUT_F * IN_F];    // dequant + perm-folded fp16
__device__ int    g_inv[IN_F];

// ---------------------------------------------------------------------------
// PTX helpers (family-common only: sm_80-level, no 'a' features)
// ---------------------------------------------------------------------------
__device__ __forceinline__ uint32_t smem_u32(const void* p) {
    uint32_t a;
    asm("{ .reg .u64 t; cvta.to.shared.u64 t, %1; cvt.u32.u64 %0, t; }"
        : "=r"(a) : "l"(p));
    return a;
}

__device__ __forceinline__ void cp_async16(uint32_t smem_addr, const void* gptr) {
    asm volatile("cp.async.cg.shared.global [%0], [%1], 16;"
                 :: "r"(smem_addr),
                    "l"((unsigned long long)__cvta_generic_to_global(gptr))
                 : "memory");
}
#define CP_COMMIT() asm volatile("cp.async.commit_group;" ::: "memory")
#define CP_WAIT(n)  asm volatile("cp.async.wait_group %0;" :: "n"(n) : "memory")

__device__ __forceinline__ uint32_t lds32(uint32_t addr) {
    uint32_t v;
    asm volatile("ld.shared.b32 %0, [%1];" : "=r"(v) : "r"(addr));
    return v;
}

// m16n8k16 fp16 MMA, fp32 accumulate.
// a0=(r,k0..k0+1) a1=(r+8,k0) a2=(r,k0+8) a3=(r+8,k0+8); b0=(c,k0) b1=(c,k0+8)
#define MMA_F16(d, a, b)                                                       \
    asm volatile(                                                              \
        "mma.sync.aligned.m16n8k16.row.col.f32.f16.f16.f32 "                   \
        "{%0,%1,%2,%3}, {%4,%5,%6,%7}, {%8,%9}, {%0,%1,%2,%3};"                \
        : "+f"((d)[0]), "+f"((d)[1]), "+f"((d)[2]), "+f"((d)[3])               \
        : "r"((a)[0]), "r"((a)[1]), "r"((a)[2]), "r"((a)[3]),                  \
          "r"((b)[0]), "r"((b)[1]))

// ---------------------------------------------------------------------------
// Prep kernels
// ---------------------------------------------------------------------------
__global__ void inv_perm_kernel(const int* __restrict__ perm) {
    int j = blockIdx.x * blockDim.x + threadIdx.x;
    if (j < IN_F) g_inv[perm[j]] = j;
}

// Dequantize + fold activation permutation into W; round to fp16.
// y[t,o] = sum_k x[t,k] * w[o, inv[k]]  ->  g_w[o][k] = dequant(w[o][inv[k]])
__global__ void prep_w_kernel(const int* __restrict__ wp, const float* __restrict__ ws) {
    __shared__ int   srow[IN_F / 2];
    __shared__ float sscale[IN_F / GS];
    int o = blockIdx.x;
    int tid = threadIdx.x;
    for (int i = tid; i < IN_F / 2; i += 256) srow[i] = wp[(size_t)o * (IN_F / 2) + i];
    if (tid < IN_F / GS) sscale[tid] = ws[(size_t)o * (IN_F / GS) + tid];
    __syncthreads();
    for (int k = tid; k < IN_F; k += 256) {
        int j = g_inv[k];                        // source (pre-perm) column
        int b = srow[j >> 1];
        int q = (((j & 1) ? (b >> 4) : b) & 0xF) - 8;
        float w = (float)q * sscale[j >> 7];     // group = j / 128
        g_w[(size_t)o * IN_F + k] = __float2half_rn(w);
    }
}

// Round x to fp16 once (float4 in -> 4 halves = 8B out).
__global__ void prep_x_kernel(const float4* __restrict__ x) {
    int i = blockIdx.x * blockDim.x + threadIdx.x;   // exact grid
    float4 v = x[i];
    __half2 h0 = __floats2half2_rn(v.x, v.y);
    __half2 h1 = __floats2half2_rn(v.z, v.w);
    __half2* p = reinterpret_cast<__half2*>(g_x);
    p[2 * i]     = h0;
    p[2 * i + 1] = h1;
}

// ---------------------------------------------------------------------------
// GEMM: 128x128 CTA tile, 3-stage cp.async pipeline, m16n8k16 fp16 MMA.
// Warp grid 4(M) x 2(N); warp tile 32x64. 2 CTAs/SM.
// smem rows are 128B (64 halves); swizzle: (seg*16) ^ ((row&7)<<4).
// ---------------------------------------------------------------------------
__device__ __forceinline__ void load_stage(uint32_t sbase, int s, int chunk,
                                           int m0, int n0, int tid) {
    uint32_t st = sbase + (uint32_t)s * STAGE_BYTES;
    const __half* gA = g_x + (size_t)m0 * IN_F + chunk * BK;
    const __half* gB = g_w + (size_t)n0 * IN_F + chunk * BK;
    #pragma unroll
    for (int it = 0; it < 4; ++it) {
        int u = tid + it * 256;                  // 0..1023
        int r = u >> 3, seg = u & 7;             // row, 16B-seg within 128B row
        uint32_t so = (uint32_t)(r * 128) + (uint32_t)((seg * 16) ^ ((r & 7) << 4));
        cp_async16(st + so,         gA + (size_t)r * IN_F + seg * 8);
        cp_async16(st + OFF_B + so, gB + (size_t)r * IN_F + seg * 8);
    }
}

__global__ void __launch_bounds__(256, 2)
gemm_kernel(const float* __restrict__ bias, float* __restrict__ out) {
    extern __shared__ char smem[];
    const uint32_t sbase = smem_u32(smem);
    const int tid  = threadIdx.x;
    const int wid  = tid >> 5;
    const int lane = tid & 31;
    const int bid  = blockIdx.x;
    const int n0 = (bid & (GRID_N - 1)) * BN;    // n-fast: W slab stays in L2
    const int m0 = (bid / GRID_N) * BM;

    const int wm = wid >> 1;                     // 0..3
    const int wn = wid & 1;                      // 0..1
    const int g  = lane >> 2;                    // 0..7
    const int t  = lane & 3;                     // 0..3
    const uint32_t mask = (uint32_t)g << 4;      // smem XOR swizzle (row&7 == g)

    float acc[2][8][4];
    #pragma unroll
    for (int i = 0; i < 2; ++i)
        #pragma unroll
        for (int j = 0; j < 8; ++j)
            #pragma unroll
            for (int c = 0; c < 4; ++c) acc[i][j][c] = 0.0f;

    // Prologue: fill STAGES-1 stages
    #pragma unroll
    for (int c = 0; c < STAGES - 1; ++c) {
        load_stage(sbase, c, c, m0, n0, tid);
        CP_COMMIT();
    }

    // Fragment row bases: A rows wm*32 + mi*16 + g (+8); B rows wn*64 + j*8 + g
    const uint32_t aRowBase = (uint32_t)((wm * 32 + g) * 128);
    const uint32_t bRowBase = (uint32_t)((wn * 64 + g) * 128) + OFF_B;
    const uint32_t t4 = (uint32_t)(t * 4);

    int s_cons = 0, s_prod = STAGES - 1;

    #pragma unroll 1
    for (int i = 0; i < NCHUNK; ++i) {
        CP_WAIT(STAGES - 2);                     // chunk i resident
        __syncthreads();
        if (i + STAGES - 1 < NCHUNK) {
            load_stage(sbase, s_prod, i + STAGES - 1, m0, n0, tid);
            if (++s_prod == STAGES) s_prod = 0;
        }
        CP_COMMIT();                             // keep group count consistent

        const uint32_t st = sbase + (uint32_t)s_cons * STAGE_BYTES;
        if (++s_cons == STAGES) s_cons = 0;
        #pragma unroll
        for (int ks = 0; ks < 4; ++ks) {         // k16 steps; 32B per step
            const uint32_t x0 = (uint32_t)((ks * 32 + t4) ^ mask);
            const uint32_t x1 = (uint32_t)((ks * 32 + t4 + 16) ^ mask);
            uint32_t ar[2][4];
            #pragma unroll
            for (int mi = 0; mi < 2; ++mi) {
                uint32_t b0 = st + aRowBase + (uint32_t)(mi * 16 * 128);
                uint32_t b1 = b0 + 8 * 128;
                ar[mi][0] = lds32(b0 + x0);      // (r,   k0)
                ar[mi][1] = lds32(b1 + x0);      // (r+8, k0)
                ar[mi][2] = lds32(b0 + x1);      // (r,   k0+8)
                ar[mi][3] = lds32(b1 + x1);      // (r+8, k0+8)
            }
            uint32_t br[8][2];
            #pragma unroll
            for (int j = 0; j < 8; ++j) {
                uint32_t nb = st + bRowBase + (uint32_t)(j * 8 * 128);
                br[j][0] = lds32(nb + x0);       // (c, k0)
                br[j][1] = lds32(nb + x1);       // (c, k0+8)
            }
            #pragma unroll
            for (int mi = 0; mi < 2; ++mi)
                #pragma unroll
                for (int j = 0; j < 8; ++j)
                    MMA_F16(acc[mi][j], ar[mi], br[j]);
        }
    }

    // Epilogue: c0/c1 at (row, 2t), c2/c3 at (row+8, 2t); add bias, float2 stores
    #pragma unroll
    for (int mi = 0; mi < 2; ++mi) {
        const int row0 = m0 + wm * 32 + mi * 16 + g;
        #pragma unroll
        for (int j = 0; j < 8; ++j) {
            const int col = n0 + wn * 64 + j * 8 + t * 2;
            const float2 b2 = *reinterpret_cast<const float2*>(bias + col);
            float2 v0, v1;
            v0.x = acc[mi][j][0] + b2.x;  v0.y = acc[mi][j][1] + b2.y;
            v1.x = acc[mi][j][2] + b2.x;  v1.y = acc[mi][j][3] + b2.y;
            *reinterpret_cast<float2*>(out + (size_t)row0 * OUT_F + col) = v0;
            *reinterpret_cast<float2*>(out + (size_t)(row0 + 8) * OUT_F + col) = v1;
        }
    }
}

// ---------------------------------------------------------------------------
// Launch
// ---------------------------------------------------------------------------
extern "C" void kernel_launch(void* const* d_in, const int* in_sizes, int n_in,
                              void* d_out, int out_size) {
    const float* x    = (const float*)d_in[0];
    const int*   wp   = (const int*)d_in[1];
    const float* ws   = (const float*)d_in[2];
    const int*   perm = (const int*)d_in[3];
    const float* bias = (const float*)d_in[4];
    float* out = (float*)d_out;

    inv_perm_kernel<<<IN_F / 256, 256>>>(perm);
    prep_w_kernel<<<OUT_F, 256>>>(wp, ws);
    prep_x_kernel<<<(TOKENS * (IN_F / 4)) / 256, 256>>>((const float4*)x);

    cudaFuncSetAttribute(gemm_kernel, cudaFuncAttributeMaxDynamicSharedMemorySize,
                         GEMM_SMEM);
    gemm_kernel<<<GRID_M * GRID_N, 256, GEMM_SMEM>>>(bias, out);
}

// round 6
// speedup vs baseline: 2.7744x; 1.1449x over previous
#include <cuda_runtime.h>
#include <cuda_fp16.h>
#include <cstdint>
#include <cstddef>

// ---------------------------------------------------------------------------
// Problem constants
// ---------------------------------------------------------------------------
#define TOKENS   8192
#define IN_F     4096
#define OUT_F    4096
#define GS       128

// GEMM tiling (fp16): BK = 64 halves = 128B rows
#define BM 128
#define BN 128
#define BK 64
#define STAGES 3                      // 96KB smem -> 2 CTAs/SM
#define NCHUNK (IN_F / BK)            // 64
#define GRID_N (OUT_F / BN)           // 32
#define GRID_M (TOKENS / BM)          // 64

#define OFF_B       (BM * BK * 2)     // 16384 (A tile bytes)
#define STAGE_BYTES ((BM + BN) * BK * 2)   // 32768
#define GEMM_SMEM   (STAGES * STAGE_BYTES) // 98304

// ---------------------------------------------------------------------------
// Device scratch (static -- no cudaMalloc anywhere)
// ---------------------------------------------------------------------------
__device__ __half g_x[(size_t)TOKENS * IN_F];   // x rounded to fp16
__device__ __half g_w[(size_t)OUT_F * IN_F];    // dequant + perm-folded fp16
__device__ int    g_inv[IN_F];

// ---------------------------------------------------------------------------
// PTX helpers (family-common: mma.sync / ldmatrix / cp.async)
// ---------------------------------------------------------------------------
__device__ __forceinline__ uint32_t smem_u32(const void* p) {
    uint32_t a;
    asm("{ .reg .u64 t; cvta.to.shared.u64 t, %1; cvt.u32.u64 %0, t; }"
        : "=r"(a) : "l"(p));
    return a;
}

__device__ __forceinline__ void cp_async16(uint32_t smem_addr, const void* gptr) {
    asm volatile("cp.async.cg.shared.global [%0], [%1], 16;"
                 :: "r"(smem_addr),
                    "l"((unsigned long long)__cvta_generic_to_global(gptr))
                 : "memory");
}
#define CP_COMMIT() asm volatile("cp.async.commit_group;" ::: "memory")
#define CP_WAIT(n)  asm volatile("cp.async.wait_group %0;" :: "n"(n) : "memory")

// ldmatrix x4: lane l supplies the row address for matrix (l>>3), row (l&7).
// Each thread receives reg i = element pair (row = l/4, cols 2(l%4)..+1) of
// matrix i -- exactly the mma.m16n8k16 fragment layout.
#define LDSM4(r, addr)                                                         \
    asm volatile("ldmatrix.sync.aligned.m8n8.x4.shared.b16 {%0,%1,%2,%3}, [%4];" \
                 : "=r"((r)[0]), "=r"((r)[1]), "=r"((r)[2]), "=r"((r)[3])      \
                 : "r"(addr))

// m16n8k16 fp16 MMA, fp32 accumulate.
#define MMA_F16(d, a, b0, b1)                                                  \
    asm volatile(                                                              \
        "mma.sync.aligned.m16n8k16.row.col.f32.f16.f16.f32 "                   \
        "{%0,%1,%2,%3}, {%4,%5,%6,%7}, {%8,%9}, {%0,%1,%2,%3};"                \
        : "+f"((d)[0]), "+f"((d)[1]), "+f"((d)[2]), "+f"((d)[3])               \
        : "r"((a)[0]), "r"((a)[1]), "r"((a)[2]), "r"((a)[3]),                  \
          "r"(b0), "r"(b1))

// ---------------------------------------------------------------------------
// Prep kernels
// ---------------------------------------------------------------------------
__global__ void inv_perm_kernel(const int* __restrict__ perm) {
    int j = blockIdx.x * blockDim.x + threadIdx.x;
    if (j < IN_F) g_inv[perm[j]] = j;
}

// Dequantize + fold activation permutation into W; round to fp16.
__global__ void prep_w_kernel(const int* __restrict__ wp, const float* __restrict__ ws) {
    __shared__ int   srow[IN_F / 2];
    __shared__ float sscale[IN_F / GS];
    int o = blockIdx.x;
    int tid = threadIdx.x;
    for (int i = tid; i < IN_F / 2; i += 256) srow[i] = wp[(size_t)o * (IN_F / 2) + i];
    if (tid < IN_F / GS) sscale[tid] = ws[(size_t)o * (IN_F / GS) + tid];
    __syncthreads();
    for (int k = tid; k < IN_F; k += 256) {
        int j = g_inv[k];                        // source (pre-perm) column
        int b = srow[j >> 1];
        int q = (((j & 1) ? (b >> 4) : b) & 0xF) - 8;
        float w = (float)q * sscale[j >> 7];     // group = j / 128
        g_w[(size_t)o * IN_F + k] = __float2half_rn(w);
    }
}

// Round x to fp16 once.
__global__ void prep_x_kernel(const float4* __restrict__ x) {
    int i = blockIdx.x * blockDim.x + threadIdx.x;   // exact grid
    float4 v = x[i];
    __half2 h0 = __floats2half2_rn(v.x, v.y);
    __half2 h1 = __floats2half2_rn(v.z, v.w);
    __half2* p = reinterpret_cast<__half2*>(g_x);
    p[2 * i]     = h0;
    p[2 * i + 1] = h1;
}

// ---------------------------------------------------------------------------
// GEMM: 128x128 CTA tile, 3-stage cp.async pipeline, m16n8k16 fp16 MMA,
// ldmatrix.x4 fragment loads. Warp grid 4(M) x 2(N); warp tile 32x64.
// smem rows are 128B (64 halves); swizzle: (seg*16) ^ ((row&7)<<4).
// ---------------------------------------------------------------------------
__device__ __forceinline__ void load_stage(uint32_t sbase, int s, int chunk,
                                           int m0, int n0, int tid) {
    uint32_t st = sbase + (uint32_t)s * STAGE_BYTES;
    const __half* gA = g_x + (size_t)m0 * IN_F + chunk * BK;
    const __half* gB = g_w + (size_t)n0 * IN_F + chunk * BK;
    #pragma unroll
    for (int it = 0; it < 4; ++it) {
        int u = tid + it * 256;                  // 0..1023
        int r = u >> 3, seg = u & 7;             // row, 16B-seg within 128B row
        uint32_t so = (uint32_t)(r * 128) + (uint32_t)((seg * 16) ^ ((r & 7) << 4));
        cp_async16(st + so,         gA + (size_t)r * IN_F + seg * 8);
        cp_async16(st + OFF_B + so, gB + (size_t)r * IN_F + seg * 8);
    }
}

__global__ void __launch_bounds__(256, 2)
gemm_kernel(const float* __restrict__ bias, float* __restrict__ out) {
    extern __shared__ char smem[];
    const uint32_t sbase = smem_u32(smem);
    const int tid  = threadIdx.x;
    const int wid  = tid >> 5;
    const int lane = tid & 31;
    const int bid  = blockIdx.x;
    const int n0 = (bid & (GRID_N - 1)) * BN;    // n-fast: W slab stays in L2
    const int m0 = (bid / GRID_N) * BM;

    const int wm = wid >> 1;                     // 0..3
    const int wn = wid & 1;                      // 0..1
    const int g  = lane >> 2;                    // 0..7
    const int t  = lane & 3;                     // 0..3

    // ldmatrix lane roles
    const int mtx = lane >> 3;                   // matrix index 0..3
    const int rr  = lane & 7;                    // row within matrix
    const uint32_t swz = (uint32_t)rr << 4;      // XOR swizzle for this row

    // A: matrix m -> rows (wm*32 + mi*16 + (m&1)*8 + rr), k-half (m>>1)
    const uint32_t aRowOff = (uint32_t)((wm * 32 + (mtx & 1) * 8 + rr) * 128);
    const uint32_t kbA = (uint32_t)((mtx >> 1) * 16);
    // B: matrix m -> rows (wn*64 + jp*16 + (m>>1)*8 + rr), k-half (m&1)
    const uint32_t bRowOff = (uint32_t)((wn * 64 + (mtx >> 1) * 8 + rr) * 128) + OFF_B;
    const uint32_t kbB = (uint32_t)((mtx & 1) * 16);

    float acc[2][8][4];
    #pragma unroll
    for (int i = 0; i < 2; ++i)
        #pragma unroll
        for (int j = 0; j < 8; ++j)
            #pragma unroll
            for (int c = 0; c < 4; ++c) acc[i][j][c] = 0.0f;

    #pragma unroll
    for (int c = 0; c < STAGES - 1; ++c) {
        load_stage(sbase, c, c, m0, n0, tid);
        CP_COMMIT();
    }

    int s_cons = 0, s_prod = STAGES - 1;

    #pragma unroll 1
    for (int i = 0; i < NCHUNK; ++i) {
        CP_WAIT(STAGES - 2);                     // chunk i resident
        __syncthreads();
        if (i + STAGES - 1 < NCHUNK) {
            load_stage(sbase, s_prod, i + STAGES - 1, m0, n0, tid);
            if (++s_prod == STAGES) s_prod = 0;
        }
        CP_COMMIT();                             // keep group count consistent

        const uint32_t st = sbase + (uint32_t)s_cons * STAGE_BYTES;
        if (++s_cons == STAGES) s_cons = 0;

        #pragma unroll
        for (int ks = 0; ks < 4; ++ks) {         // k16 steps; 32B per step
            const uint32_t colA = ((uint32_t)(ks * 32) + kbA) ^ swz;
            const uint32_t colB = ((uint32_t)(ks * 32) + kbB) ^ swz;
            uint32_t ar[2][4];
            LDSM4(ar[0], st + aRowOff + colA);              // mi=0 (rows +0)
            LDSM4(ar[1], st + aRowOff + 16 * 128 + colA);   // mi=1 (rows +16)
            #pragma unroll
            for (int jp = 0; jp < 4; ++jp) {     // j pair: regs 0,1 = j even; 2,3 = j odd
                uint32_t bq[4];
                LDSM4(bq, st + bRowOff + (uint32_t)(jp * 16 * 128) + colB);
                MMA_F16(acc[0][jp * 2],     ar[0], bq[0], bq[1]);
                MMA_F16(acc[1][jp * 2],     ar[1], bq[0], bq[1]);
                MMA_F16(acc[0][jp * 2 + 1], ar[0], bq[2], bq[3]);
                MMA_F16(acc[1][jp * 2 + 1], ar[1], bq[2], bq[3]);
            }
        }
    }

    // Epilogue: c0/c1 at (row, 2t), c2/c3 at (row+8, 2t); add bias, float2 stores
    #pragma unroll
    for (int mi = 0; mi < 2; ++mi) {
        const int row0 = m0 + wm * 32 + mi * 16 + g;
        #pragma unroll
        for (int j = 0; j < 8; ++j) {
            const int col = n0 + wn * 64 + j * 8 + t * 2;
            const float2 b2 = *reinterpret_cast<const float2*>(bias + col);
            float2 v0, v1;
            v0.x = acc[mi][j][0] + b2.x;  v0.y = acc[mi][j][1] + b2.y;
            v1.x = acc[mi][j][2] + b2.x;  v1.y = acc[mi][j][3] + b2.y;
            *reinterpret_cast<float2*>(out + (size_t)row0 * OUT_F + col) = v0;
            *reinterpret_cast<float2*>(out + (size_t)(row0 + 8) * OUT_F + col) = v1;
        }
    }
}

// ---------------------------------------------------------------------------
// Launch
// ---------------------------------------------------------------------------
extern "C" void kernel_launch(void* const* d_in, const int* in_sizes, int n_in,
                              void* d_out, int out_size) {
    const float* x    = (const float*)d_in[0];
    const int*   wp   = (const int*)d_in[1];
    const float* ws   = (const float*)d_in[2];
    const int*   perm = (const int*)d_in[3];
    const float* bias = (const float*)d_in[4];
    float* out = (float*)d_out;

    inv_perm_kernel<<<IN_F / 256, 256>>>(perm);
    prep_w_kernel<<<OUT_F, 256>>>(wp, ws);
    prep_x_kernel<<<(TOKENS * (IN_F / 4)) / 256, 256>>>((const float4*)x);

    cudaFuncSetAttribute(gemm_kernel, cudaFuncAttributeMaxDynamicSharedMemorySize,
                         GEMM_SMEM);
    gemm_kernel<<<GRID_M * GRID_N, 256, GEMM_SMEM>>>(bias, out);
}